// round 17
// baseline (speedup 1.0000x reference)
#include <cuda_runtime.h>
#include <cuda_bf16.h>
#include <cstdint>

#define N_ATOMS_MAX 50000
#define CDIM 64
#define ROW  (3 * CDIM)   // 192 floats per atom

// Static scratch (no allocations allowed).
__device__ float          g_agg[N_ATOMS_MAX * ROW];   // 38.4 MB
__device__ __nv_bfloat16  g_wh[CDIM * CDIM];          // W hi  (row-major [d][c])
__device__ __nv_bfloat16  g_wl[CDIM * CDIM];          // W lo residual

// ---------------------------------------------------------------------------
// Pair kernel (unchanged — measured at the LTS byte cap, ~114 us).
// ---------------------------------------------------------------------------
__global__ void pair_kernel(const int* __restrict__ ind,
                            const float* __restrict__ p3,
                            const float* __restrict__ i1,
                            const float* __restrict__ d3,
                            float* __restrict__ agg,
                            int n_pairs)
{
    int t = blockIdx.x * blockDim.x + threadIdx.x;
    int pair = t >> 4;
    if (pair >= n_pairs) return;
    int lane = t & 15;

    int ai = ind[2 * pair + 0];
    int aj = ind[2 * pair + 1];

    float4 g = *reinterpret_cast<const float4*>(i1 + (size_t)pair * CDIM + lane * 4);
    float dv[3];
    dv[0] = d3[3 * pair + 0];
    dv[1] = d3[3 * pair + 1];
    dv[2] = d3[3 * pair + 2];

    const float4* pj = reinterpret_cast<const float4*>(p3 + (size_t)aj * ROW);
    float4*       pa = reinterpret_cast<float4*>(agg + (size_t)ai * ROW);

#pragma unroll
    for (int x = 0; x < 3; x++) {
        float4 v = pj[x * 16 + lane];
        float dx = dv[x];
        float r0 = (v.x + dx) * g.x;
        float r1 = (v.y + dx) * g.y;
        float r2 = (v.z + dx) * g.z;
        float r3 = (v.w + dx) * g.w;
        asm volatile("red.global.add.v4.f32 [%0], {%1, %2, %3, %4};"
                     :: "l"(pa + x * 16 + lane),
                        "f"(r0), "f"(r1), "f"(r2), "f"(r3) : "memory");
    }
}

// ---------------------------------------------------------------------------
// W prep: fp32 -> bf16 hi + lo residual (row-major, tiny).
// ---------------------------------------------------------------------------
__global__ void wprep_kernel(const float* __restrict__ W,
                             __nv_bfloat16* __restrict__ wh,
                             __nv_bfloat16* __restrict__ wl)
{
    int i = blockIdx.x * blockDim.x + threadIdx.x;
    if (i < CDIM * CDIM) {
        float f = W[i];
        __nv_bfloat16 h = __float2bfloat16_rn(f);
        wh[i] = h;
        wl[i] = __float2bfloat16_rn(f - __bfloat162float(h));
    }
}

// ---------------------------------------------------------------------------
// GEMM via mma.sync m16n8k16 bf16 (sm_80+ baseline PTX — no 'a' feature).
//   D[M=150000, 64] = A @ W^T,  A = agg viewed as [M, 64].
// Block: 8 warps x 16 rows = 128 rows. Each warp: 16x64 output tile.
// A frags: direct LDG float2 + in-register hi/lo bf16 split (no smem).
// W frags: hi/lo bf16 in smem, row pad 36 u32 -> conflict-free b-frag reads.
// 3-term compensated: Ah*Wh + Al*Wh + Ah*Wl.
// ---------------------------------------------------------------------------
__device__ __forceinline__ uint32_t pbf2(float lo_e, float hi_e) {
    // pack {low half: lo_e, high half: hi_e} as bf16x2  (PTX: cvt d, hi, lo)
    uint32_t r;
    asm("cvt.rn.bf16x2.f32 %0, %1, %2;" : "=r"(r) : "f"(hi_e), "f"(lo_e));
    return r;
}
__device__ __forceinline__ void split_pack(float2 v, uint32_t& h, uint32_t& l) {
    float h0 = __bfloat162float(__float2bfloat16_rn(v.x));
    float h1 = __bfloat162float(__float2bfloat16_rn(v.y));
    h = pbf2(h0, h1);
    l = pbf2(v.x - h0, v.y - h1);
}
__device__ __forceinline__ void mma_bf16(float* c, const uint32_t* a,
                                         uint32_t b0, uint32_t b1) {
    asm volatile(
        "mma.sync.aligned.m16n8k16.row.col.f32.bf16.bf16.f32 "
        "{%0,%1,%2,%3}, {%4,%5,%6,%7}, {%8,%9}, {%0,%1,%2,%3};"
        : "+f"(c[0]), "+f"(c[1]), "+f"(c[2]), "+f"(c[3])
        : "r"(a[0]), "r"(a[1]), "r"(a[2]), "r"(a[3]), "r"(b0), "r"(b1));
}

#define WPAD 36   // u32 per W row in smem (68 bf16 padded to 72)

__global__ void __launch_bounds__(256) gemm_mma_kernel(
    const float* __restrict__ agg,
    const __nv_bfloat16* __restrict__ wh16,
    const __nv_bfloat16* __restrict__ wl16,
    float* __restrict__ p3_new,
    int M)
{
    __shared__ uint32_t sW[2][CDIM][WPAD];   // [hi/lo][d][k-pair]

    int tid = threadIdx.x;
    // stage W hi/lo (each row = 32 u32 of bf16x2 pairs)
    {
        const uint32_t* wh = reinterpret_cast<const uint32_t*>(wh16);
        const uint32_t* wl = reinterpret_cast<const uint32_t*>(wl16);
        for (int i = tid; i < CDIM * 32; i += 256) {
            int d = i >> 5, kp = i & 31;
            sW[0][d][kp] = wh[d * 32 + kp];
            sW[1][d][kp] = wl[d * 32 + kp];
        }
    }
    __syncthreads();

    int warp = tid >> 5;
    int lane = tid & 31;
    int r0 = blockIdx.x * 128 + warp * 16 + (lane >> 2);   // this thread's row
    int qk = (lane & 3) * 2;                               // k pair base (t%4)*2

    bool ok0 = (r0 < M);
    bool ok8 = (r0 + 8 < M);

    float acc[8][4];
#pragma unroll
    for (int n = 0; n < 8; n++)
#pragma unroll
        for (int k = 0; k < 4; k++) acc[n][k] = 0.f;

#pragma unroll
    for (int ks = 0; ks < 4; ks++) {
        int k0 = ks * 16 + qk;
        float2 z = make_float2(0.f, 0.f);
        float2 a00 = ok0 ? *reinterpret_cast<const float2*>(agg + (size_t)r0 * 64 + k0) : z;
        float2 a10 = ok8 ? *reinterpret_cast<const float2*>(agg + (size_t)(r0 + 8) * 64 + k0) : z;
        float2 a01 = ok0 ? *reinterpret_cast<const float2*>(agg + (size_t)r0 * 64 + k0 + 8) : z;
        float2 a11 = ok8 ? *reinterpret_cast<const float2*>(agg + (size_t)(r0 + 8) * 64 + k0 + 8) : z;

        uint32_t ah[4], al[4];
        split_pack(a00, ah[0], al[0]);
        split_pack(a10, ah[1], al[1]);
        split_pack(a01, ah[2], al[2]);
        split_pack(a11, ah[3], al[3]);

        int drow = lane >> 2;          // d offset within n-chunk
        int kp   = ks * 8 + (lane & 3);
#pragma unroll
        for (int nc = 0; nc < 8; nc++) {
            uint32_t bh0 = sW[0][nc * 8 + drow][kp];
            uint32_t bh1 = sW[0][nc * 8 + drow][kp + 4];
            uint32_t bl0 = sW[1][nc * 8 + drow][kp];
            uint32_t bl1 = sW[1][nc * 8 + drow][kp + 4];
            mma_bf16(acc[nc], ah, bh0, bh1);
            mma_bf16(acc[nc], al, bh0, bh1);
            mma_bf16(acc[nc], ah, bl0, bl1);
        }
    }

    // store D frags: thread covers rows r0, r0+8; cols nc*8 + (lane%4)*2
    int cbase = (lane & 3) * 2;
#pragma unroll
    for (int nc = 0; nc < 8; nc++) {
        int c = nc * 8 + cbase;
        if (ok0)
            *reinterpret_cast<float2*>(p3_new + (size_t)r0 * 64 + c) =
                make_float2(acc[nc][0], acc[nc][1]);
        if (ok8)
            *reinterpret_cast<float2*>(p3_new + (size_t)(r0 + 8) * 64 + c) =
                make_float2(acc[nc][2], acc[nc][3]);
    }
}

// ---------------------------------------------------------------------------
// dotted[a,d] = sum_x p3_new[a,x,d]^2.  One thread per (a, 2 d's), float2.
// ---------------------------------------------------------------------------
__global__ void __launch_bounds__(256) dotted_kernel(
    const float* __restrict__ p3_new,
    float* __restrict__ dotted,
    int n_atoms)
{
    int t = blockIdx.x * blockDim.x + threadIdx.x;
    int a  = t >> 5;
    if (a >= n_atoms) return;
    int d2 = (t & 31) * 2;

    const float2* base = reinterpret_cast<const float2*>(p3_new + (size_t)a * ROW + d2);
    float2 v0 = base[0];
    float2 v1 = base[32];    // +64 floats
    float2 v2 = base[64];    // +128 floats
    float2 r;
    r.x = v0.x * v0.x + v1.x * v1.x + v2.x * v2.x;
    r.y = v0.y * v0.y + v1.y * v1.y + v2.y * v2.y;
    *reinterpret_cast<float2*>(dotted + (size_t)a * CDIM + d2) = r;
}

// ---------------------------------------------------------------------------
// Inputs (metadata order): ind_2 [P,2] i32, p3 [A,3,64] f32, i1 [P,64] f32,
// d3 [P,3] f32, W [64,64] f32.  Output: p3_new [A,3,64] ++ dotted [A,64].
// ---------------------------------------------------------------------------
extern "C" void kernel_launch(void* const* d_in, const int* in_sizes, int n_in,
                              void* d_out, int out_size)
{
    const int*   ind = (const int*)  d_in[0];
    const float* p3  = (const float*)d_in[1];
    const float* i1  = (const float*)d_in[2];
    const float* d3  = (const float*)d_in[3];
    const float* W   = (const float*)d_in[4];

    int n_pairs = in_sizes[0] / 2;
    int n_atoms = in_sizes[1] / ROW;
    int M = n_atoms * 3;                 // flat gemm rows

    float* p3_new = (float*)d_out;
    float* dotted = (float*)d_out + (size_t)n_atoms * ROW;

    float* agg; __nv_bfloat16 *wh, *wl;
    cudaGetSymbolAddress((void**)&agg, g_agg);
    cudaGetSymbolAddress((void**)&wh,  g_wh);
    cudaGetSymbolAddress((void**)&wl,  g_wl);

    // 1) zero accumulator
    cudaMemsetAsync(agg, 0, (size_t)n_atoms * ROW * sizeof(float));

    // 2) W bf16 hi/lo prep (tiny)
    wprep_kernel<<<(CDIM * CDIM + 255) / 256, 256>>>(W, wh, wl);

    // 3) pair scatter-reduce
    {
        int total = n_pairs * 16;
        pair_kernel<<<(total + 255) / 256, 256>>>(ind, p3, i1, d3, agg, n_pairs);
    }

    // 4) tensor-core GEMM (mma.sync bf16, 3-term compensated)
    {
        int blocks = (M + 127) / 128;
        gemm_mma_kernel<<<blocks, 256>>>(agg, wh, wl, p3_new, M);
    }

    // 5) dotted epilogue
    {
        int total = n_atoms * 32;
        dotted_kernel<<<(total + 255) / 256, 256>>>(p3_new, dotted, n_atoms);
    }
}